// round 11
// baseline (speedup 1.0000x reference)
#include <cuda_runtime.h>

#define BB 256
#define TT 500
#define NC 100
#define NA 13

// ---------------------------------------------------------------------------
// Fully fused kernel: one block per batch element (256 threads, 8 warps).
//   0) stage: per-warp segment [w*63,(w+1)*63): stream FM rows (4/iter,
//      8 LDG.128 in flight), dot with lr_w (butterfly reduce), combine with
//      olp/olk deltas -> s_z; also stage per-chain T/init tables.
//   1) parallel stable counting sort of timesteps by chain (8 warps)
//   2) balanced per-chain sweep (alpha in regs, prefetched), Gy -> smem
//   3) post 1a: per-chunk log-prefix of Gy materialized to s_abil
//   4) post 2: thread-per-row linear-space lse (no shuffles, 3 logf/row)
// dynamic smem: s_G[TT*NA] + s_abil[TT*NA] = 52000 B
// ---------------------------------------------------------------------------
__global__ void __launch_bounds__(256) bkt_kernel(
    const int* __restrict__ corr, const int* __restrict__ kc,
    const int* __restrict__ prob, const float* __restrict__ trans_logits,
    const float* __restrict__ olp, const float* __restrict__ olk,
    const float* __restrict__ init_logits, const float* __restrict__ FM,
    const float* __restrict__ lr_w, const float* __restrict__ lr_b,
    float* __restrict__ out) {
    extern __shared__ float dsm[];
    float* s_G    = dsm;            // Gy per (t, a)            26000 B
    float* s_abil = dsm + TT * NA;  // chunk-local prefix       26000 B

    __shared__ float4 s_z[TT];           // (sy*D0, sy*D1, sy, 0)   8000 B
    __shared__ float4 s_w0[50];          // lr_w row 0               800 B
    __shared__ float4 s_w1[50];          // lr_w row 1               800 B
    __shared__ float4 s_T[NC];           // trans probs             1600 B
    __shared__ float2 s_init[NC];        //                          800 B
    __shared__ int    s_kc[TT];          //                         2000 B
    __shared__ int    s_ord[TT];         //                         2000 B
    __shared__ int    s_start[NC + 4];   //                          416 B
    __shared__ int    s_cnt8[8][NC];     //                         3200 B
    __shared__ float  s_csum[8][NA];
    __shared__ float  s_carry[8][NA];

    const int b = blockIdx.x;
    const int tid = threadIdx.x;
    const int wid = tid >> 5;
    const int lane = tid & 31;
    const int laneA = (lane < NA) ? lane : 0;
    const float ab2 = 2.f * (-3.0f + 0.5f * (float)laneA);
    const int t0 = wid * 63;
    const int t1 = min(t0 + 63, TT);

    const float4* olp4 = (const float4*)olp;
    const float4* olk4 = (const float4*)olk;
    const float4* tl4  = (const float4*)trans_logits;

    // ---- stage weights / chain tables / zero histograms ----
    if (tid < 50) {
        s_w0[tid] = ((const float4*)lr_w)[tid];
        s_w1[tid] = ((const float4*)lr_w)[50 + tid];
    }
    for (int i = tid; i < 8 * NC; i += 256) (&s_cnt8[0][0])[i] = 0;
    if (tid < NC) {
        float4 t = __ldg(tl4 + tid);
        float m0 = fmaxf(t.x, t.z), m1 = fmaxf(t.y, t.w);
        float e00 = __expf(t.x - m0), e10 = __expf(t.z - m0);
        float e01 = __expf(t.y - m1), e11 = __expf(t.w - m1);
        float r0 = __fdividef(1.f, e00 + e10);
        float r1 = __fdividef(1.f, e01 + e11);
        s_T[tid] = make_float4(e00 * r0, e01 * r1, e10 * r0, e11 * r1);
        float2 il = ((const float2*)init_logits)[tid];
        float m = fmaxf(il.x, il.y);
        float ex = __expf(il.x - m), ey = __expf(il.y - m);
        float ri = __fdividef(1.f, ex + ey);
        s_init[tid] = make_float2(ex * ri, ey * ri);
    }
    const float lrb0 = __ldg(lr_b), lrb1 = __ldg(lr_b + 1);
    __syncthreads();

    // ---- fused x + z staging: 4 rows per iteration per warp ----
    const bool tail18 = lane < 18;
    for (int r = t0; r < t1; r += 4) {
        const int nrows = min(4, t1 - r);
        // lanes 0-3 own row r+lane's metadata; prefetch olp/olk early
        int cL = 0, yL = 0;
        float4 opv = make_float4(0.f, 0.f, 0.f, 0.f), okv = opv;
        if (lane < nrows) {
            int tL = b * TT + r + lane;
            cL = __ldg(kc + tL);
            int pL = __ldg(prob + tL);
            yL = __ldg(corr + tL);
            opv = __ldg(olp4 + pL);
            okv = __ldg(olk4 + cL);
        }
        // FM loads: 8 LDG.128 in flight
        float4 A0, A1, A2, A3, B0, B1, B2, B3;
        const float4* fp = (const float4*)(FM + (size_t)(b * TT + r) * 200);
        A0 = __ldg(fp + lane);
        if (nrows > 1) A1 = __ldg(fp + 50 + lane);
        if (nrows > 2) A2 = __ldg(fp + 100 + lane);
        if (nrows > 3) A3 = __ldg(fp + 150 + lane);
        if (tail18) {
            B0 = __ldg(fp + 32 + lane);
            if (nrows > 1) B1 = __ldg(fp + 82 + lane);
            if (nrows > 2) B2 = __ldg(fp + 132 + lane);
            if (nrows > 3) B3 = __ldg(fp + 182 + lane);
        }
        float4 u = s_w0[lane], s = s_w1[lane];
        float d00 = A0.x*u.x + A0.y*u.y + A0.z*u.z + A0.w*u.w;
        float d01 = A0.x*s.x + A0.y*s.y + A0.z*s.z + A0.w*s.w;
        float d10 = 0.f, d11 = 0.f, d20 = 0.f, d21 = 0.f, d30 = 0.f, d31 = 0.f;
        if (nrows > 1) {
            d10 = A1.x*u.x + A1.y*u.y + A1.z*u.z + A1.w*u.w;
            d11 = A1.x*s.x + A1.y*s.y + A1.z*s.z + A1.w*s.w;
        }
        if (nrows > 2) {
            d20 = A2.x*u.x + A2.y*u.y + A2.z*u.z + A2.w*u.w;
            d21 = A2.x*s.x + A2.y*s.y + A2.z*s.z + A2.w*s.w;
        }
        if (nrows > 3) {
            d30 = A3.x*u.x + A3.y*u.y + A3.z*u.z + A3.w*u.w;
            d31 = A3.x*s.x + A3.y*s.y + A3.z*s.z + A3.w*s.w;
        }
        if (tail18) {
            float4 u2 = s_w0[32 + lane], s2 = s_w1[32 + lane];
            d00 += B0.x*u2.x + B0.y*u2.y + B0.z*u2.z + B0.w*u2.w;
            d01 += B0.x*s2.x + B0.y*s2.y + B0.z*s2.z + B0.w*s2.w;
            if (nrows > 1) {
                d10 += B1.x*u2.x + B1.y*u2.y + B1.z*u2.z + B1.w*u2.w;
                d11 += B1.x*s2.x + B1.y*s2.y + B1.z*s2.z + B1.w*s2.w;
            }
            if (nrows > 2) {
                d20 += B2.x*u2.x + B2.y*u2.y + B2.z*u2.z + B2.w*u2.w;
                d21 += B2.x*s2.x + B2.y*s2.y + B2.z*s2.z + B2.w*s2.w;
            }
            if (nrows > 3) {
                d30 += B3.x*u2.x + B3.y*u2.y + B3.z*u2.z + B3.w*u2.w;
                d31 += B3.x*s2.x + B3.y*s2.y + B3.z*s2.z + B3.w*s2.w;
            }
        }
#pragma unroll
        for (int off = 16; off; off >>= 1) {
            d00 += __shfl_xor_sync(0xffffffffu, d00, off);
            d01 += __shfl_xor_sync(0xffffffffu, d01, off);
            d10 += __shfl_xor_sync(0xffffffffu, d10, off);
            d11 += __shfl_xor_sync(0xffffffffu, d11, off);
            d20 += __shfl_xor_sync(0xffffffffu, d20, off);
            d21 += __shfl_xor_sync(0xffffffffu, d21, off);
            d30 += __shfl_xor_sync(0xffffffffu, d30, off);
            d31 += __shfl_xor_sync(0xffffffffu, d31, off);
        }
        // butterfly left sums in ALL lanes; lane i finalizes row r+i
        if (lane < nrows) {
            float x0 = (lane == 0) ? d00 : (lane == 1) ? d10 : (lane == 2) ? d20 : d30;
            float x1 = (lane == 0) ? d01 : (lane == 1) ? d11 : (lane == 2) ? d21 : d31;
            x0 += lrb0; x1 += lrb1;
            float sy = yL ? 1.f : -1.f;
            float D0 = (opv.y - opv.x) + (okv.y - okv.x) - 2.f * x0;
            float D1 = (opv.w - opv.z) + (okv.w - okv.z) - 2.f * x1;
            s_z[r + lane] = make_float4(sy * D0, sy * D1, sy, 0.f);
            s_kc[r + lane] = cL;
        }
    }
    __syncthreads();

    // ---- sort pass 1: per-segment histogram ----
    for (int t = t0 + lane; t < t1; t += 32) atomicAdd(&s_cnt8[wid][s_kc[t]], 1);
    __syncthreads();
    // ---- per-chain exclusive prefix over segments; chain totals ----
    if (tid < NC) {
        int run = 0;
#pragma unroll
        for (int w = 0; w < 8; ++w) {
            int v = s_cnt8[w][tid];
            s_cnt8[w][tid] = run;
            run += v;
        }
        s_start[tid] = run;  // total per chain (temp)
    }
    __syncthreads();
    // ---- exclusive scan over 100 chain totals (warp 0) ----
    if (wid == 0) {
        int base4 = lane * 4;
        int v0 = 0, v1 = 0, v2 = 0, v3 = 0;
        if (lane < 25) {
            v0 = s_start[base4]; v1 = s_start[base4 + 1];
            v2 = s_start[base4 + 2]; v3 = s_start[base4 + 3];
        }
        int sum = v0 + v1 + v2 + v3;
        int inc = sum;
#pragma unroll
        for (int off = 1; off < 32; off <<= 1) {
            int n = __shfl_up_sync(0xffffffffu, inc, off);
            if (lane >= off) inc += n;
        }
        int ex = inc - sum;
        if (lane < 25) {
            s_start[base4]     = ex;
            s_start[base4 + 1] = ex + v0;
            s_start[base4 + 2] = ex + v0 + v1;
            s_start[base4 + 3] = ex + v0 + v1 + v2;
        }
        if (lane == 24) s_start[NC] = ex + sum;  // == TT
    }
    __syncthreads();
    // ---- add chain bases into per-segment offsets ----
    if (tid < NC) {
        int st = s_start[tid];
#pragma unroll
        for (int w = 0; w < 8; ++w) s_cnt8[w][tid] += st;
    }
    __syncthreads();
    // ---- sort pass 2: fill (order-preserving; all 8 warps) ----
    for (int base = t0; base < t1; base += 32) {
        int t = base + lane;
        bool valid = t < t1;
        unsigned am = __ballot_sync(0xffffffffu, valid);
        if (valid) {
            int c = s_kc[t];
            unsigned m = __match_any_sync(am, c);
            int rank = __popc(m & ((1u << lane) - 1u));
            int b0 = s_cnt8[wid][c];
            s_ord[b0 + rank] = t;
            int leader = 31 - __clz(m);
            if (lane == leader) s_cnt8[wid][c] = b0 + __popc(m);
        }
        __syncwarp();
    }
    __syncthreads();

    // ---- balanced sweep: chain c -> warp s_start[c]/63; prefetched ----
    for (int c = 0; c < NC; ++c) {
        int st = s_start[c], en = s_start[c + 1];
        if (st == en) continue;
        if (((st * 1041) >> 16) != wid) continue;
        float2 Ai = s_init[c];
        float A0 = Ai.x, A1 = Ai.y;
        float4 T = s_T[c];
        int t = s_ord[st];
        float4 zz = s_z[t];
        for (int i = st; i < en; ++i) {
            int tn = (i + 1 < en) ? s_ord[i + 1] : 0;
            float4 zn = s_z[tn];
            float z0 = fmaf(zz.z, ab2, zz.x);
            float z1 = fmaf(zz.z, ab2, zz.y);
            float f0 = 1.f + __expf(-z0);    // 1/p0
            float f1 = 1.f + __expf(-z1);    // 1/p1
            float v0 = A0 * f1, v1 = A1 * f0;
            float sS = v0 + v1;
            float Gy = __fdividef(sS, f0 * f1);
            if (lane < NA) s_G[t * NA + lane] = Gy;
            float r = __fdividef(1.f, sS);
            A0 = fmaf(v0, T.x, v1 * T.y) * r;
            A1 = fmaf(v0, T.z, v1 * T.w) * r;
            t = tn; zz = zn;
        }
    }
    __syncthreads();

    // ---- post 1a: chunk-local prefix of log(Gy), materialized ----
    if (lane < NA) {
        float acc = 0.f;
        for (int t = t0; t < t1; ++t) {
            float lgy = __logf(s_G[t * NA + lane]);
            s_abil[t * NA + lane] = acc;  // prefix BEFORE including step t
            acc += lgy;
        }
        s_csum[wid][lane] = acc;
    }
    __syncthreads();
    if (wid == 0 && lane < NA) {
        float run = -2.5649493574615367f;  // -log(13)
#pragma unroll
        for (int w = 0; w < 8; ++w) {
            s_carry[w][lane] = run;
            run += s_csum[w][lane];
        }
    }
    __syncthreads();

    // ---- post 2: thread-per-row, linear space ----
#pragma unroll
    for (int rr = 0; rr < 2; ++rr) {
        int t = tid + rr * 256;
        if (t >= TT) break;
        int ch = (t * 1041) >> 16;  // t / 63 for t < 504
        float ab[NA], G[NA];
        float M = -1e30f;
#pragma unroll
        for (int a = 0; a < NA; ++a) {
            G[a]  = s_G[t * NA + a];
            ab[a] = s_abil[t * NA + a] + s_carry[ch][a];
            M = fmaxf(M, ab[a]);
        }
        float Sy = 0.f, So = 0.f;
#pragma unroll
        for (int a = 0; a < NA; ++a) {
            float E = __expf(ab[a] - M);
            Sy = fmaf(E, G[a], Sy);
            So = fmaf(E, 1.f - G[a], So);
        }
        bool y = s_z[t].z > 0.f;
        float ly = __logf(Sy), lo = __logf(So), ls = __logf(Sy + So);
        float o0 = (y ? lo : ly) - ls;
        float o1 = (y ? ly : lo) - ls;
        ((float2*)out)[b * TT + t] = make_float2(o0, o1);
    }
}

// ---------------------------------------------------------------------------
// inputs: 0 corr[i32 B,T] 1 kc 2 problem 3 FM[f32 B,T,200]
//         4 trans_logits[f32 100,2,2] 5 obs_logits_problem[f32 10000,2,2]
//         6 obs_logits_kc[f32 100,2,2] 7 init_logits[f32 100,2]
//         8 lr_w[f32 2,200] 9 lr_b[f32 2]     output: f32 [B,T,2]
// ---------------------------------------------------------------------------
extern "C" void kernel_launch(void* const* d_in, const int* in_sizes, int n_in,
                              void* d_out, int out_size) {
    const int*   corr = (const int*)d_in[0];
    const int*   kcp  = (const int*)d_in[1];
    const int*   prob = (const int*)d_in[2];
    const float* FM   = (const float*)d_in[3];
    const float* tl   = (const float*)d_in[4];
    const float* olp  = (const float*)d_in[5];
    const float* olk  = (const float*)d_in[6];
    const float* il   = (const float*)d_in[7];
    const float* lrw  = (const float*)d_in[8];
    const float* lrb  = (const float*)d_in[9];
    float* out = (float*)d_out;

    const int DSMEM = TT * NA * 2 * (int)sizeof(float);  // 52000 B
    cudaFuncSetAttribute(bkt_kernel, cudaFuncAttributeMaxDynamicSharedMemorySize, DSMEM);

    bkt_kernel<<<BB, 256, DSMEM>>>(corr, kcp, prob, tl, olp, olk, il,
                                   FM, lrw, lrb, out);
}

// round 12
// speedup vs baseline: 1.0409x; 1.0409x over previous
#include <cuda_runtime.h>

#define BB 256
#define TT 500
#define NC 100
#define NA 13

// scratch: x = FM @ lr_w^T + lr_b  [B,T,2]
__device__ float g_x[BB * TT * 2];

__device__ __forceinline__ void grid_dep_trigger() {
    asm volatile("griddepcontrol.launch_dependents;");
}
__device__ __forceinline__ void grid_dep_wait() {
    asm volatile("griddepcontrol.wait;" ::: "memory");
}

// ---------------------------------------------------------------------------
// Kernel 1: x[b,t,o] = sum_f FM[b,t,f] * lr_w[o,f] + lr_b[o]
// Four rows per warp -> 8 independent LDG.128 in flight. Triggers dependent
// launch at entry so bkt_kernel's pre-wait phases co-run with this stream.
// ---------------------------------------------------------------------------
__global__ void __launch_bounds__(256) x_kernel(const float* __restrict__ FM,
                                                const float* __restrict__ lr_w,
                                                const float* __restrict__ lr_b) {
    grid_dep_trigger();
    __shared__ float4 w0[50], w1[50];
    int tid = threadIdx.x;
    if (tid < 50) {
        w0[tid] = ((const float4*)lr_w)[tid];
        w1[tid] = ((const float4*)lr_w)[50 + tid];
    }
    __syncthreads();
    int lane = tid & 31;
    int r = (blockIdx.x * 8 + (tid >> 5)) * 4;  // rows r..r+3
    if (r >= BB * TT) return;
    const float4* fp = (const float4*)(FM + (size_t)r * 200);
    bool tail = lane < 18;

    float4 A0 = __ldg(fp + lane);
    float4 A1 = __ldg(fp + 50 + lane);
    float4 A2 = __ldg(fp + 100 + lane);
    float4 A3 = __ldg(fp + 150 + lane);
    float4 B0, B1, B2, B3;
    if (tail) {
        B0 = __ldg(fp + 32 + lane);
        B1 = __ldg(fp + 82 + lane);
        B2 = __ldg(fp + 132 + lane);
        B3 = __ldg(fp + 182 + lane);
    }
    float4 u = w0[lane], s = w1[lane];
    float d00 = A0.x*u.x + A0.y*u.y + A0.z*u.z + A0.w*u.w;
    float d01 = A0.x*s.x + A0.y*s.y + A0.z*s.z + A0.w*s.w;
    float d10 = A1.x*u.x + A1.y*u.y + A1.z*u.z + A1.w*u.w;
    float d11 = A1.x*s.x + A1.y*s.y + A1.z*s.z + A1.w*s.w;
    float d20 = A2.x*u.x + A2.y*u.y + A2.z*u.z + A2.w*u.w;
    float d21 = A2.x*s.x + A2.y*s.y + A2.z*s.z + A2.w*s.w;
    float d30 = A3.x*u.x + A3.y*u.y + A3.z*u.z + A3.w*u.w;
    float d31 = A3.x*s.x + A3.y*s.y + A3.z*s.z + A3.w*s.w;
    if (tail) {
        float4 u2 = w0[32 + lane], s2 = w1[32 + lane];
        d00 += B0.x*u2.x + B0.y*u2.y + B0.z*u2.z + B0.w*u2.w;
        d01 += B0.x*s2.x + B0.y*s2.y + B0.z*s2.z + B0.w*s2.w;
        d10 += B1.x*u2.x + B1.y*u2.y + B1.z*u2.z + B1.w*u2.w;
        d11 += B1.x*s2.x + B1.y*s2.y + B1.z*s2.z + B1.w*s2.w;
        d20 += B2.x*u2.x + B2.y*u2.y + B2.z*u2.z + B2.w*u2.w;
        d21 += B2.x*s2.x + B2.y*s2.y + B2.z*s2.z + B2.w*s2.w;
        d30 += B3.x*u2.x + B3.y*u2.y + B3.z*u2.z + B3.w*u2.w;
        d31 += B3.x*s2.x + B3.y*s2.y + B3.z*s2.z + B3.w*s2.w;
    }
#pragma unroll
    for (int off = 16; off; off >>= 1) {
        d00 += __shfl_xor_sync(0xffffffffu, d00, off);
        d01 += __shfl_xor_sync(0xffffffffu, d01, off);
        d10 += __shfl_xor_sync(0xffffffffu, d10, off);
        d11 += __shfl_xor_sync(0xffffffffu, d11, off);
        d20 += __shfl_xor_sync(0xffffffffu, d20, off);
        d21 += __shfl_xor_sync(0xffffffffu, d21, off);
        d30 += __shfl_xor_sync(0xffffffffu, d30, off);
        d31 += __shfl_xor_sync(0xffffffffu, d31, off);
    }
    if (lane == 0) {
        float bb0 = __ldg(lr_b), bb1 = __ldg(lr_b + 1);
        ((float4*)g_x)[(r >> 1)]     = make_float4(d00 + bb0, d01 + bb1, d10 + bb0, d11 + bb1);
        ((float4*)g_x)[(r >> 1) + 1] = make_float4(d20 + bb0, d21 + bb1, d30 + bb0, d31 + bb1);
    }
}

// ---------------------------------------------------------------------------
// Kernel 2: per-batch block (256 threads, 8 warps). PDL-overlapped:
//   PRE-WAIT  (runs under x_kernel): stage chain tables + okd deltas,
//             kc/prob/corr loads + olp gathers -> partial D, counting sort.
//   griddepcontrol.wait
//   POST-WAIT: fold g_x into D; balanced per-chain sweep (alpha in regs);
//              post 1a: parallel logf batch + FADD-only serial prefix;
//              post 2: thread-per-row linear-space lse.
// dynamic smem: s_G[TT*NA] + s_abil[TT*NA] = 52000 B
// ---------------------------------------------------------------------------
__global__ void __launch_bounds__(256) bkt_kernel(
    const int* __restrict__ corr, const int* __restrict__ kc,
    const int* __restrict__ prob, const float* __restrict__ trans_logits,
    const float* __restrict__ olp, const float* __restrict__ olk,
    const float* __restrict__ init_logits, float* __restrict__ out) {
    extern __shared__ float dsm[];
    float* s_G    = dsm;            // Gy per (t, a)            26000 B
    float* s_abil = dsm + TT * NA;  // logs, then prefix        26000 B

    __shared__ float4 s_z[TT];           // (Dp0/D0, Dp1/D1, sy, 0) 8000 B
    __shared__ float4 s_T[NC];           // trans probs             1600 B
    __shared__ float2 s_init[NC];        //                          800 B
    __shared__ float2 s_okd[NC];         // olk deltas               800 B
    __shared__ int    s_kc[TT];          //                         2000 B
    __shared__ int    s_ord[TT];         //                         2000 B
    __shared__ int    s_start[NC + 4];   //                          416 B
    __shared__ int    s_cnt8[8][NC];     //                         3200 B
    __shared__ float  s_csum[8][NA];
    __shared__ float  s_carry[8][NA];

    const int b = blockIdx.x;
    const int tid = threadIdx.x;
    const int wid = tid >> 5;
    const int lane = tid & 31;
    const int laneA = (lane < NA) ? lane : 0;
    const float ab2 = 2.f * (-3.0f + 0.5f * (float)laneA);
    const int t0 = wid * 63;
    const int t1 = min(t0 + 63, TT);

    const float4* olp4 = (const float4*)olp;
    const float4* olk4 = (const float4*)olk;
    const float4* tl4  = (const float4*)trans_logits;

    // ================= PRE-WAIT PHASE (overlaps x_kernel) =================
    for (int i = tid; i < 8 * NC; i += 256) (&s_cnt8[0][0])[i] = 0;
    if (tid < NC) {
        float4 t = __ldg(tl4 + tid);
        float m0 = fmaxf(t.x, t.z), m1 = fmaxf(t.y, t.w);
        float e00 = __expf(t.x - m0), e10 = __expf(t.z - m0);
        float e01 = __expf(t.y - m1), e11 = __expf(t.w - m1);
        float r0 = __fdividef(1.f, e00 + e10);
        float r1 = __fdividef(1.f, e01 + e11);
        s_T[tid] = make_float4(e00 * r0, e01 * r1, e10 * r0, e11 * r1);
        float2 il = ((const float2*)init_logits)[tid];
        float m = fmaxf(il.x, il.y);
        float ex = __expf(il.x - m), ey = __expf(il.y - m);
        float ri = __fdividef(1.f, ex + ey);
        s_init[tid] = make_float2(ex * ri, ey * ri);
        float4 ok = __ldg(olk4 + tid);
        s_okd[tid] = make_float2(ok.y - ok.x, ok.w - ok.z);
    }
    __syncthreads();

    // per-t: partial D (no x yet): Dp_s = d_olp_s + d_olk_s ; store sy
    for (int i = tid; i < TT; i += 256) {
        int c = kc[b * TT + i];
        int p = prob[b * TT + i];
        int y = corr[b * TT + i];
        s_kc[i] = c;
        float4 op = __ldg(olp4 + p);
        float2 okd = s_okd[c];
        float sy = y ? 1.f : -1.f;
        s_z[i] = make_float4((op.y - op.x) + okd.x, (op.w - op.z) + okd.y, sy, 0.f);
    }
    __syncthreads();

    // ---- sort pass 1: per-segment histogram ----
    for (int t = t0 + lane; t < t1; t += 32) atomicAdd(&s_cnt8[wid][s_kc[t]], 1);
    __syncthreads();
    if (tid < NC) {
        int run = 0;
#pragma unroll
        for (int w = 0; w < 8; ++w) {
            int v = s_cnt8[w][tid];
            s_cnt8[w][tid] = run;
            run += v;
        }
        s_start[tid] = run;  // total per chain (temp)
    }
    __syncthreads();
    if (wid == 0) {
        int base4 = lane * 4;
        int v0 = 0, v1 = 0, v2 = 0, v3 = 0;
        if (lane < 25) {
            v0 = s_start[base4]; v1 = s_start[base4 + 1];
            v2 = s_start[base4 + 2]; v3 = s_start[base4 + 3];
        }
        int sum = v0 + v1 + v2 + v3;
        int inc = sum;
#pragma unroll
        for (int off = 1; off < 32; off <<= 1) {
            int n = __shfl_up_sync(0xffffffffu, inc, off);
            if (lane >= off) inc += n;
        }
        int ex = inc - sum;
        if (lane < 25) {
            s_start[base4]     = ex;
            s_start[base4 + 1] = ex + v0;
            s_start[base4 + 2] = ex + v0 + v1;
            s_start[base4 + 3] = ex + v0 + v1 + v2;
        }
        if (lane == 24) s_start[NC] = ex + sum;  // == TT
    }
    __syncthreads();
    if (tid < NC) {
        int st = s_start[tid];
#pragma unroll
        for (int w = 0; w < 8; ++w) s_cnt8[w][tid] += st;
    }
    __syncthreads();
    for (int base = t0; base < t1; base += 32) {
        int t = base + lane;
        bool valid = t < t1;
        unsigned am = __ballot_sync(0xffffffffu, valid);
        if (valid) {
            int c = s_kc[t];
            unsigned m = __match_any_sync(am, c);
            int rank = __popc(m & ((1u << lane) - 1u));
            int b0 = s_cnt8[wid][c];
            s_ord[b0 + rank] = t;
            int leader = 31 - __clz(m);
            if (lane == leader) s_cnt8[wid][c] = b0 + __popc(m);
        }
        __syncwarp();
    }

    // ================= WAIT FOR x_kernel =================
    grid_dep_wait();

    // fold x into D: D_s = sy * (Dp_s - 2*x_s)
    const float2* gx2 = (const float2*)g_x;
    for (int i = tid; i < TT; i += 256) {
        float2 xv = gx2[b * TT + i];
        float4 z = s_z[i];
        z.x = z.z * (z.x - 2.f * xv.x);
        z.y = z.z * (z.y - 2.f * xv.y);
        s_z[i] = z;
    }
    __syncthreads();

    // ---- balanced sweep: chain c -> warp s_start[c]/63; prefetched ----
    for (int c = 0; c < NC; ++c) {
        int st = s_start[c], en = s_start[c + 1];
        if (st == en) continue;
        if (((st * 1041) >> 16) != wid) continue;
        float2 Ai = s_init[c];
        float A0 = Ai.x, A1 = Ai.y;
        float4 T = s_T[c];
        int t = s_ord[st];
        float4 zz = s_z[t];
        for (int i = st; i < en; ++i) {
            int tn = (i + 1 < en) ? s_ord[i + 1] : 0;
            float4 zn = s_z[tn];
            float z0 = fmaf(zz.z, ab2, zz.x);
            float z1 = fmaf(zz.z, ab2, zz.y);
            float f0 = 1.f + __expf(-z0);    // 1/p0
            float f1 = 1.f + __expf(-z1);    // 1/p1
            float v0 = A0 * f1, v1 = A1 * f0;
            float sS = v0 + v1;
            float Gy = __fdividef(sS, f0 * f1);
            if (lane < NA) s_G[t * NA + lane] = Gy;
            float r = __fdividef(1.f, sS);
            A0 = fmaf(v0, T.x, v1 * T.y) * r;
            A1 = fmaf(v0, T.z, v1 * T.w) * r;
            t = tn; zz = zn;
        }
    }
    __syncthreads();

    // ---- post 1a-A: batch all logf(Gy) (all 256 threads, throughput) ----
    for (int i = tid; i < TT * NA; i += 256) s_abil[i] = __logf(s_G[i]);
    __syncthreads();
    // ---- post 1a-B: FADD-only serial prefix, in place ----
    if (lane < NA) {
        float nxt = s_abil[t0 * NA + lane];
        float acc = 0.f;
        for (int t = t0; t < t1; ++t) {
            float lg = nxt;
            if (t + 1 < t1) nxt = s_abil[(t + 1) * NA + lane];
            s_abil[t * NA + lane] = acc;  // prefix BEFORE step t
            acc += lg;
        }
        s_csum[wid][lane] = acc;
    }
    __syncthreads();
    if (wid == 0 && lane < NA) {
        float run = -2.5649493574615367f;  // -log(13)
#pragma unroll
        for (int w = 0; w < 8; ++w) {
            s_carry[w][lane] = run;
            run += s_csum[w][lane];
        }
    }
    __syncthreads();

    // ---- post 2: thread-per-row, linear space ----
#pragma unroll
    for (int rr = 0; rr < 2; ++rr) {
        int t = tid + rr * 256;
        if (t >= TT) break;
        int ch = (t * 1041) >> 16;  // t / 63 for t < 504
        float ab[NA], G[NA];
        float M = -1e30f;
#pragma unroll
        for (int a = 0; a < NA; ++a) {
            G[a]  = s_G[t * NA + a];
            ab[a] = s_abil[t * NA + a] + s_carry[ch][a];
            M = fmaxf(M, ab[a]);
        }
        float Sy = 0.f, So = 0.f;
#pragma unroll
        for (int a = 0; a < NA; ++a) {
            float E = __expf(ab[a] - M);
            Sy = fmaf(E, G[a], Sy);
            So = fmaf(E, 1.f - G[a], So);
        }
        bool y = s_z[t].z > 0.f;
        float ly = __logf(Sy), lo = __logf(So), ls = __logf(Sy + So);
        float o0 = (y ? lo : ly) - ls;
        float o1 = (y ? ly : lo) - ls;
        ((float2*)out)[b * TT + t] = make_float2(o0, o1);
    }
}

// ---------------------------------------------------------------------------
// inputs: 0 corr[i32 B,T] 1 kc 2 problem 3 FM[f32 B,T,200]
//         4 trans_logits[f32 100,2,2] 5 obs_logits_problem[f32 10000,2,2]
//         6 obs_logits_kc[f32 100,2,2] 7 init_logits[f32 100,2]
//         8 lr_w[f32 2,200] 9 lr_b[f32 2]     output: f32 [B,T,2]
// ---------------------------------------------------------------------------
extern "C" void kernel_launch(void* const* d_in, const int* in_sizes, int n_in,
                              void* d_out, int out_size) {
    const int*   corr = (const int*)d_in[0];
    const int*   kcp  = (const int*)d_in[1];
    const int*   prob = (const int*)d_in[2];
    const float* FM   = (const float*)d_in[3];
    const float* tl   = (const float*)d_in[4];
    const float* olp  = (const float*)d_in[5];
    const float* olk  = (const float*)d_in[6];
    const float* il   = (const float*)d_in[7];
    const float* lrw  = (const float*)d_in[8];
    const float* lrb  = (const float*)d_in[9];
    float* out = (float*)d_out;

    const int DSMEM = TT * NA * 2 * (int)sizeof(float);  // 52000 B
    cudaFuncSetAttribute(bkt_kernel, cudaFuncAttributeMaxDynamicSharedMemorySize, DSMEM);

    // primary: x_kernel (triggers dependent launch at entry)
    x_kernel<<<(BB * TT / 4 + 7) / 8, 256>>>(FM, lrw, lrb);

    // secondary: bkt_kernel with Programmatic Dependent Launch
    cudaLaunchConfig_t cfg = {};
    cfg.gridDim = dim3(BB, 1, 1);
    cfg.blockDim = dim3(256, 1, 1);
    cfg.dynamicSmemBytes = DSMEM;
    cfg.stream = 0;
    cudaLaunchAttribute attrs[1];
    attrs[0].id = cudaLaunchAttributeProgrammaticStreamSerialization;
    attrs[0].val.programmaticStreamSerializationAllowed = 1;
    cfg.attrs = attrs;
    cfg.numAttrs = 1;
    cudaLaunchKernelEx(&cfg, bkt_kernel, corr, kcp, prob, tl, olp, olk, il, out);
}

// round 13
// speedup vs baseline: 1.1766x; 1.1304x over previous
#include <cuda_runtime.h>

#define BB 256
#define TT 500
#define NC 100
#define NA 13
#define NW 16          // warps per bkt block
#define CH 32          // timesteps per warp segment (16*32 = 512 >= 500)

// scratch: x = FM @ lr_w^T + lr_b  [B,T,2]
__device__ float g_x[BB * TT * 2];

// ---------------------------------------------------------------------------
// Kernel 1: x[b,t,o] = sum_f FM[b,t,f] * lr_w[o,f] + lr_b[o]
// Four rows per warp -> 8 independent LDG.128 in flight.
// ---------------------------------------------------------------------------
__global__ void __launch_bounds__(256) x_kernel(const float* __restrict__ FM,
                                                const float* __restrict__ lr_w,
                                                const float* __restrict__ lr_b) {
    __shared__ float4 w0[50], w1[50];
    int tid = threadIdx.x;
    if (tid < 50) {
        w0[tid] = ((const float4*)lr_w)[tid];
        w1[tid] = ((const float4*)lr_w)[50 + tid];
    }
    __syncthreads();
    int lane = tid & 31;
    int r = (blockIdx.x * 8 + (tid >> 5)) * 4;  // rows r..r+3
    if (r >= BB * TT) return;
    const float4* fp = (const float4*)(FM + (size_t)r * 200);
    bool tail = lane < 18;

    float4 A0 = __ldg(fp + lane);
    float4 A1 = __ldg(fp + 50 + lane);
    float4 A2 = __ldg(fp + 100 + lane);
    float4 A3 = __ldg(fp + 150 + lane);
    float4 B0, B1, B2, B3;
    if (tail) {
        B0 = __ldg(fp + 32 + lane);
        B1 = __ldg(fp + 82 + lane);
        B2 = __ldg(fp + 132 + lane);
        B3 = __ldg(fp + 182 + lane);
    }
    float4 u = w0[lane], s = w1[lane];
    float d00 = A0.x*u.x + A0.y*u.y + A0.z*u.z + A0.w*u.w;
    float d01 = A0.x*s.x + A0.y*s.y + A0.z*s.z + A0.w*s.w;
    float d10 = A1.x*u.x + A1.y*u.y + A1.z*u.z + A1.w*u.w;
    float d11 = A1.x*s.x + A1.y*s.y + A1.z*s.z + A1.w*s.w;
    float d20 = A2.x*u.x + A2.y*u.y + A2.z*u.z + A2.w*u.w;
    float d21 = A2.x*s.x + A2.y*s.y + A2.z*s.z + A2.w*s.w;
    float d30 = A3.x*u.x + A3.y*u.y + A3.z*u.z + A3.w*u.w;
    float d31 = A3.x*s.x + A3.y*s.y + A3.z*s.z + A3.w*s.w;
    if (tail) {
        float4 u2 = w0[32 + lane], s2 = w1[32 + lane];
        d00 += B0.x*u2.x + B0.y*u2.y + B0.z*u2.z + B0.w*u2.w;
        d01 += B0.x*s2.x + B0.y*s2.y + B0.z*s2.z + B0.w*s2.w;
        d10 += B1.x*u2.x + B1.y*u2.y + B1.z*u2.z + B1.w*u2.w;
        d11 += B1.x*s2.x + B1.y*s2.y + B1.z*s2.z + B1.w*s2.w;
        d20 += B2.x*u2.x + B2.y*u2.y + B2.z*u2.z + B2.w*u2.w;
        d21 += B2.x*s2.x + B2.y*s2.y + B2.z*s2.z + B2.w*s2.w;
        d30 += B3.x*u2.x + B3.y*u2.y + B3.z*u2.z + B3.w*u2.w;
        d31 += B3.x*s2.x + B3.y*s2.y + B3.z*s2.z + B3.w*s2.w;
    }
#pragma unroll
    for (int off = 16; off; off >>= 1) {
        d00 += __shfl_xor_sync(0xffffffffu, d00, off);
        d01 += __shfl_xor_sync(0xffffffffu, d01, off);
        d10 += __shfl_xor_sync(0xffffffffu, d10, off);
        d11 += __shfl_xor_sync(0xffffffffu, d11, off);
        d20 += __shfl_xor_sync(0xffffffffu, d20, off);
        d21 += __shfl_xor_sync(0xffffffffu, d21, off);
        d30 += __shfl_xor_sync(0xffffffffu, d30, off);
        d31 += __shfl_xor_sync(0xffffffffu, d31, off);
    }
    if (lane == 0) {
        float bb0 = __ldg(lr_b), bb1 = __ldg(lr_b + 1);
        ((float4*)g_x)[(r >> 1)]     = make_float4(d00 + bb0, d01 + bb1, d10 + bb0, d11 + bb1);
        ((float4*)g_x)[(r >> 1) + 1] = make_float4(d20 + bb0, d21 + bb1, d30 + bb0, d31 + bb1);
    }
}

// ---------------------------------------------------------------------------
// Kernel 2 (fused): per-batch block, 16 warps / 512 threads.
//   1) stage z-table + per-chain T/init
//   2) parallel stable counting sort of timesteps by chain (16 warps)
//   3) balanced per-chain sweep (alpha in regs, prefetched), Gy -> smem
//   4) post 1a: per-chunk (32-step) log-prefix of Gy materialized to s_abil
//   5) post 2: thread-per-row linear-space lse (one row per thread)
// dynamic smem: s_G[TT*NA] + s_abil[TT*NA] = 52000 B
// ---------------------------------------------------------------------------
__global__ void __launch_bounds__(512) bkt_kernel(
    const int* __restrict__ corr, const int* __restrict__ kc,
    const int* __restrict__ prob, const float* __restrict__ trans_logits,
    const float* __restrict__ olp, const float* __restrict__ olk,
    const float* __restrict__ init_logits, float* __restrict__ out) {
    extern __shared__ float dsm[];
    float* s_G    = dsm;            // Gy per (t, a)            26000 B
    float* s_abil = dsm + TT * NA;  // chunk-local prefix       26000 B

    __shared__ float4 s_z[TT];           // (sy*D0, sy*D1, sy, 0)   8000 B
    __shared__ float4 s_T[NC];           // trans probs             1600 B
    __shared__ float2 s_init[NC];        //                          800 B
    __shared__ float2 s_okd[NC];         // olk deltas               800 B
    __shared__ int    s_kc[TT];          //                         2000 B
    __shared__ int    s_ord[TT];         //                         2000 B
    __shared__ int    s_start[NC + 4];   //                          416 B
    __shared__ int    s_cnt[NW][NC];     //                         6400 B
    __shared__ float  s_csum[NW][NA];
    __shared__ float  s_carry[NW][NA];

    const int b = blockIdx.x;
    const int tid = threadIdx.x;
    const int wid = tid >> 5;
    const int lane = tid & 31;
    const int laneA = (lane < NA) ? lane : 0;
    const float ab2 = 2.f * (-3.0f + 0.5f * (float)laneA);
    const int t0 = wid * CH;
    const int t1 = min(t0 + CH, TT);

    const float4* olp4 = (const float4*)olp;
    const float4* olk4 = (const float4*)olk;
    const float4* tl4  = (const float4*)trans_logits;
    const float2* gx2  = (const float2*)g_x;

    // ---- stage chain tables; zero histograms ----
    for (int i = tid; i < NW * NC; i += 512) (&s_cnt[0][0])[i] = 0;
    if (tid < NC) {
        float4 t = __ldg(tl4 + tid);
        float m0 = fmaxf(t.x, t.z), m1 = fmaxf(t.y, t.w);
        float e00 = __expf(t.x - m0), e10 = __expf(t.z - m0);
        float e01 = __expf(t.y - m1), e11 = __expf(t.w - m1);
        float r0 = __fdividef(1.f, e00 + e10);
        float r1 = __fdividef(1.f, e01 + e11);
        s_T[tid] = make_float4(e00 * r0, e01 * r1, e10 * r0, e11 * r1);
        float2 il = ((const float2*)init_logits)[tid];
        float m = fmaxf(il.x, il.y);
        float ex = __expf(il.x - m), ey = __expf(il.y - m);
        float ri = __fdividef(1.f, ex + ey);
        s_init[tid] = make_float2(ex * ri, ey * ri);
        float4 ok = __ldg(olk4 + tid);
        s_okd[tid] = make_float2(ok.y - ok.x, ok.w - ok.z);
    }
    __syncthreads();

    // ---- stage z table + kc ----
    for (int i = tid; i < TT; i += 512) {
        int c = kc[b * TT + i];
        int p = prob[b * TT + i];
        int y = corr[b * TT + i];
        s_kc[i] = c;
        float4 op = __ldg(olp4 + p);
        float2 okd = s_okd[c];
        float2 xv = gx2[b * TT + i];
        float sy = y ? 1.f : -1.f;
        float D0 = (op.y - op.x) + okd.x - 2.f * xv.x;
        float D1 = (op.w - op.z) + okd.y - 2.f * xv.y;
        s_z[i] = make_float4(sy * D0, sy * D1, sy, 0.f);
    }
    __syncthreads();

    // ---- sort pass 1: per-segment histogram ----
    for (int t = t0 + lane; t < t1; t += 32) atomicAdd(&s_cnt[wid][s_kc[t]], 1);
    __syncthreads();
    // ---- per-chain exclusive prefix over segments; chain totals ----
    if (tid < NC) {
        int run = 0;
#pragma unroll
        for (int w = 0; w < NW; ++w) {
            int v = s_cnt[w][tid];
            s_cnt[w][tid] = run;
            run += v;
        }
        s_start[tid] = run;  // total per chain (temp)
    }
    __syncthreads();
    // ---- exclusive scan over 100 chain totals (warp 0) ----
    if (wid == 0) {
        int base4 = lane * 4;
        int v0 = 0, v1 = 0, v2 = 0, v3 = 0;
        if (lane < 25) {
            v0 = s_start[base4]; v1 = s_start[base4 + 1];
            v2 = s_start[base4 + 2]; v3 = s_start[base4 + 3];
        }
        int sum = v0 + v1 + v2 + v3;
        int inc = sum;
#pragma unroll
        for (int off = 1; off < 32; off <<= 1) {
            int n = __shfl_up_sync(0xffffffffu, inc, off);
            if (lane >= off) inc += n;
        }
        int ex = inc - sum;
        if (lane < 25) {
            s_start[base4]     = ex;
            s_start[base4 + 1] = ex + v0;
            s_start[base4 + 2] = ex + v0 + v1;
            s_start[base4 + 3] = ex + v0 + v1 + v2;
        }
        if (lane == 24) s_start[NC] = ex + sum;  // == TT
    }
    __syncthreads();
    // ---- add chain bases into per-segment offsets ----
    if (tid < NC) {
        int st = s_start[tid];
#pragma unroll
        for (int w = 0; w < NW; ++w) s_cnt[w][tid] += st;
    }
    __syncthreads();
    // ---- sort pass 2: fill (order-preserving; all warps, one 32-chunk) ----
    {
        int t = t0 + lane;
        bool valid = t < t1;
        unsigned am = __ballot_sync(0xffffffffu, valid);
        if (valid) {
            int c = s_kc[t];
            unsigned m = __match_any_sync(am, c);
            int rank = __popc(m & ((1u << lane) - 1u));
            int b0 = s_cnt[wid][c];
            s_ord[b0 + rank] = t;
        }
    }
    __syncthreads();

    // ---- balanced sweep: chain c -> warp s_start[c]/32; prefetched ----
    for (int c = 0; c < NC; ++c) {
        int st = s_start[c], en = s_start[c + 1];
        if (st == en) continue;
        if ((st >> 5) != wid) continue;
        float2 Ai = s_init[c];
        float A0 = Ai.x, A1 = Ai.y;
        float4 T = s_T[c];
        int t = s_ord[st];
        float4 zz = s_z[t];
        for (int i = st; i < en; ++i) {
            int tn = (i + 1 < en) ? s_ord[i + 1] : 0;
            float4 zn = s_z[tn];
            float z0 = fmaf(zz.z, ab2, zz.x);
            float z1 = fmaf(zz.z, ab2, zz.y);
            float f0 = 1.f + __expf(-z0);    // 1/p0
            float f1 = 1.f + __expf(-z1);    // 1/p1
            float v0 = A0 * f1, v1 = A1 * f0;
            float sS = v0 + v1;
            float Gy = __fdividef(sS, f0 * f1);
            if (lane < NA) s_G[t * NA + lane] = Gy;
            float r = __fdividef(1.f, sS);
            A0 = fmaf(v0, T.x, v1 * T.y) * r;
            A1 = fmaf(v0, T.z, v1 * T.w) * r;
            t = tn; zz = zn;
        }
    }
    __syncthreads();

    // ---- post 1a: chunk-local prefix of log(Gy), materialized ----
    if (lane < NA) {
        float acc = 0.f;
        for (int t = t0; t < t1; ++t) {
            float lgy = __logf(s_G[t * NA + lane]);
            s_abil[t * NA + lane] = acc;  // prefix BEFORE including step t
            acc += lgy;
        }
        s_csum[wid][lane] = acc;
    }
    __syncthreads();
    if (wid == 0 && lane < NA) {
        float run = -2.5649493574615367f;  // -log(13)
#pragma unroll
        for (int w = 0; w < NW; ++w) {
            s_carry[w][lane] = run;
            run += s_csum[w][lane];
        }
    }
    __syncthreads();

    // ---- post 2: thread-per-row, linear space ----
    {
        int t = tid;
        if (t < TT) {
            int ch = t >> 5;
            float ab[NA], G[NA];
            float M = -1e30f;
#pragma unroll
            for (int a = 0; a < NA; ++a) {
                G[a]  = s_G[t * NA + a];
                ab[a] = s_abil[t * NA + a] + s_carry[ch][a];
                M = fmaxf(M, ab[a]);
            }
            float Sy = 0.f, So = 0.f;
#pragma unroll
            for (int a = 0; a < NA; ++a) {
                float E = __expf(ab[a] - M);
                Sy = fmaf(E, G[a], Sy);
                So = fmaf(E, 1.f - G[a], So);
            }
            bool y = s_z[t].z > 0.f;
            float ly = __logf(Sy), lo = __logf(So), ls = __logf(Sy + So);
            float o0 = (y ? lo : ly) - ls;
            float o1 = (y ? ly : lo) - ls;
            ((float2*)out)[b * TT + t] = make_float2(o0, o1);
        }
    }
}

// ---------------------------------------------------------------------------
// inputs: 0 corr[i32 B,T] 1 kc 2 problem 3 FM[f32 B,T,200]
//         4 trans_logits[f32 100,2,2] 5 obs_logits_problem[f32 10000,2,2]
//         6 obs_logits_kc[f32 100,2,2] 7 init_logits[f32 100,2]
//         8 lr_w[f32 2,200] 9 lr_b[f32 2]     output: f32 [B,T,2]
// ---------------------------------------------------------------------------
extern "C" void kernel_launch(void* const* d_in, const int* in_sizes, int n_in,
                              void* d_out, int out_size) {
    const int*   corr = (const int*)d_in[0];
    const int*   kcp  = (const int*)d_in[1];
    const int*   prob = (const int*)d_in[2];
    const float* FM   = (const float*)d_in[3];
    const float* tl   = (const float*)d_in[4];
    const float* olp  = (const float*)d_in[5];
    const float* olk  = (const float*)d_in[6];
    const float* il   = (const float*)d_in[7];
    const float* lrw  = (const float*)d_in[8];
    const float* lrb  = (const float*)d_in[9];
    float* out = (float*)d_out;

    const int DSMEM = TT * NA * 2 * (int)sizeof(float);  // 52000 B
    cudaFuncSetAttribute(bkt_kernel, cudaFuncAttributeMaxDynamicSharedMemorySize, DSMEM);

    x_kernel<<<(BB * TT / 4 + 7) / 8, 256>>>(FM, lrw, lrb);
    bkt_kernel<<<BB, 512, DSMEM>>>(corr, kcp, prob, tl, olp, olk, il, out);
}

// round 14
// speedup vs baseline: 1.4362x; 1.2206x over previous
#include <cuda_runtime.h>

#define BB 256
#define TT 500
#define NC 100
#define NA 13
#define NW 16          // warps per bkt block
#define CH 32          // timesteps per warp segment for sort (16*32 >= 500)
#define NH 32          // half-warps per block
#define CH2 16         // timesteps per half-warp chunk (32*16 >= 500)

// scratch: x = FM @ lr_w^T + lr_b  [B,T,2]
__device__ float g_x[BB * TT * 2];

// ---------------------------------------------------------------------------
// Kernel 1: x[b,t,o] = sum_f FM[b,t,f] * lr_w[o,f] + lr_b[o]
// Four rows per warp -> 8 independent LDG.128 in flight.
// ---------------------------------------------------------------------------
__global__ void __launch_bounds__(256) x_kernel(const float* __restrict__ FM,
                                                const float* __restrict__ lr_w,
                                                const float* __restrict__ lr_b) {
    __shared__ float4 w0[50], w1[50];
    int tid = threadIdx.x;
    if (tid < 50) {
        w0[tid] = ((const float4*)lr_w)[tid];
        w1[tid] = ((const float4*)lr_w)[50 + tid];
    }
    __syncthreads();
    int lane = tid & 31;
    int r = (blockIdx.x * 8 + (tid >> 5)) * 4;  // rows r..r+3
    if (r >= BB * TT) return;
    const float4* fp = (const float4*)(FM + (size_t)r * 200);
    bool tail = lane < 18;

    float4 A0 = __ldg(fp + lane);
    float4 A1 = __ldg(fp + 50 + lane);
    float4 A2 = __ldg(fp + 100 + lane);
    float4 A3 = __ldg(fp + 150 + lane);
    float4 B0, B1, B2, B3;
    if (tail) {
        B0 = __ldg(fp + 32 + lane);
        B1 = __ldg(fp + 82 + lane);
        B2 = __ldg(fp + 132 + lane);
        B3 = __ldg(fp + 182 + lane);
    }
    float4 u = w0[lane], s = w1[lane];
    float d00 = A0.x*u.x + A0.y*u.y + A0.z*u.z + A0.w*u.w;
    float d01 = A0.x*s.x + A0.y*s.y + A0.z*s.z + A0.w*s.w;
    float d10 = A1.x*u.x + A1.y*u.y + A1.z*u.z + A1.w*u.w;
    float d11 = A1.x*s.x + A1.y*s.y + A1.z*s.z + A1.w*s.w;
    float d20 = A2.x*u.x + A2.y*u.y + A2.z*u.z + A2.w*u.w;
    float d21 = A2.x*s.x + A2.y*s.y + A2.z*s.z + A2.w*s.w;
    float d30 = A3.x*u.x + A3.y*u.y + A3.z*u.z + A3.w*u.w;
    float d31 = A3.x*s.x + A3.y*s.y + A3.z*s.z + A3.w*s.w;
    if (tail) {
        float4 u2 = w0[32 + lane], s2 = w1[32 + lane];
        d00 += B0.x*u2.x + B0.y*u2.y + B0.z*u2.z + B0.w*u2.w;
        d01 += B0.x*s2.x + B0.y*s2.y + B0.z*s2.z + B0.w*s2.w;
        d10 += B1.x*u2.x + B1.y*u2.y + B1.z*u2.z + B1.w*u2.w;
        d11 += B1.x*s2.x + B1.y*s2.y + B1.z*s2.z + B1.w*s2.w;
        d20 += B2.x*u2.x + B2.y*u2.y + B2.z*u2.z + B2.w*u2.w;
        d21 += B2.x*s2.x + B2.y*s2.y + B2.z*s2.z + B2.w*s2.w;
        d30 += B3.x*u2.x + B3.y*u2.y + B3.z*u2.z + B3.w*u2.w;
        d31 += B3.x*s2.x + B3.y*s2.y + B3.z*s2.z + B3.w*s2.w;
    }
#pragma unroll
    for (int off = 16; off; off >>= 1) {
        d00 += __shfl_xor_sync(0xffffffffu, d00, off);
        d01 += __shfl_xor_sync(0xffffffffu, d01, off);
        d10 += __shfl_xor_sync(0xffffffffu, d10, off);
        d11 += __shfl_xor_sync(0xffffffffu, d11, off);
        d20 += __shfl_xor_sync(0xffffffffu, d20, off);
        d21 += __shfl_xor_sync(0xffffffffu, d21, off);
        d30 += __shfl_xor_sync(0xffffffffu, d30, off);
        d31 += __shfl_xor_sync(0xffffffffu, d31, off);
    }
    if (lane == 0) {
        float bb0 = __ldg(lr_b), bb1 = __ldg(lr_b + 1);
        ((float4*)g_x)[(r >> 1)]     = make_float4(d00 + bb0, d01 + bb1, d10 + bb0, d11 + bb1);
        ((float4*)g_x)[(r >> 1) + 1] = make_float4(d20 + bb0, d21 + bb1, d30 + bb0, d31 + bb1);
    }
}

// ---------------------------------------------------------------------------
// Kernel 2 (fused): per-batch block, 16 warps / 512 threads.
//   1) stage z-table + per-chain tables
//   2) parallel stable counting sort -> packed flat schedule
//      s_ordc[i] = t | (c<<9) | (first<<31), grouped by chain, time-ordered
//   3) sweep: 32 HALF-warps each walk a contiguous schedule range;
//      data-driven alpha resets; 13 active lanes per half
//   4) post 1a: 32 half-warp chunks (16 steps) log-prefix -> s_abil
//   5) post 2: thread-per-row linear-space lse
// dynamic smem: s_G[TT*NA] + s_abil[TT*NA] = 52000 B
// ---------------------------------------------------------------------------
__global__ void __launch_bounds__(512) bkt_kernel(
    const int* __restrict__ corr, const int* __restrict__ kc,
    const int* __restrict__ prob, const float* __restrict__ trans_logits,
    const float* __restrict__ olp, const float* __restrict__ olk,
    const float* __restrict__ init_logits, float* __restrict__ out) {
    extern __shared__ float dsm[];
    float* s_G    = dsm;            // Gy per (t, a)            26000 B
    float* s_abil = dsm + TT * NA;  // chunk-local prefix       26000 B

    __shared__ float4 s_z[TT];           // (sy*D0, sy*D1, sy, 0)   8000 B
    __shared__ float4 s_T[NC];           // trans probs             1600 B
    __shared__ float2 s_init[NC];        //                          800 B
    __shared__ float2 s_okd[NC];         // olk deltas               800 B
    __shared__ int    s_kc[TT];          //                         2000 B
    __shared__ int    s_ordc[TT];        // packed schedule         2000 B
    __shared__ int    s_start[NC + 4];   //                          416 B
    __shared__ int    s_cnt[NW][NC];     //                         6400 B
    __shared__ int    s_hwlo[NH + 1];    // half-warp ranges         132 B
    __shared__ float  s_csum[NH][NA];
    __shared__ float  s_carry[NH][NA];

    const int b = blockIdx.x;
    const int tid = threadIdx.x;
    const int wid = tid >> 5;
    const int lane = tid & 31;
    const int la = lane & 15;                 // lane within half-warp
    const int laneA = (la < NA) ? la : 0;
    const float ab2 = 2.f * (-3.0f + 0.5f * (float)laneA);
    const int t0 = wid * CH;
    const int t1 = min(t0 + CH, TT);

    const float4* olp4 = (const float4*)olp;
    const float4* olk4 = (const float4*)olk;
    const float4* tl4  = (const float4*)trans_logits;
    const float2* gx2  = (const float2*)g_x;

    // ---- stage chain tables; zero histograms; init group bounds ----
    for (int i = tid; i < NW * NC; i += 512) (&s_cnt[0][0])[i] = 0;
    if (tid < NH) s_hwlo[tid] = 0x7fffffff;
    if (tid == NH) s_hwlo[NH] = TT;
    if (tid < NC) {
        float4 t = __ldg(tl4 + tid);
        float m0 = fmaxf(t.x, t.z), m1 = fmaxf(t.y, t.w);
        float e00 = __expf(t.x - m0), e10 = __expf(t.z - m0);
        float e01 = __expf(t.y - m1), e11 = __expf(t.w - m1);
        float r0 = __fdividef(1.f, e00 + e10);
        float r1 = __fdividef(1.f, e01 + e11);
        s_T[tid] = make_float4(e00 * r0, e01 * r1, e10 * r0, e11 * r1);
        float2 il = ((const float2*)init_logits)[tid];
        float m = fmaxf(il.x, il.y);
        float ex = __expf(il.x - m), ey = __expf(il.y - m);
        float ri = __fdividef(1.f, ex + ey);
        s_init[tid] = make_float2(ex * ri, ey * ri);
        float4 ok = __ldg(olk4 + tid);
        s_okd[tid] = make_float2(ok.y - ok.x, ok.w - ok.z);
    }
    __syncthreads();

    // ---- stage z table + kc ----
    for (int i = tid; i < TT; i += 512) {
        int c = kc[b * TT + i];
        int p = prob[b * TT + i];
        int y = corr[b * TT + i];
        s_kc[i] = c;
        float4 op = __ldg(olp4 + p);
        float2 okd = s_okd[c];
        float2 xv = gx2[b * TT + i];
        float sy = y ? 1.f : -1.f;
        float D0 = (op.y - op.x) + okd.x - 2.f * xv.x;
        float D1 = (op.w - op.z) + okd.y - 2.f * xv.y;
        s_z[i] = make_float4(sy * D0, sy * D1, sy, 0.f);
    }
    __syncthreads();

    // ---- sort pass 1: per-segment histogram ----
    for (int t = t0 + lane; t < t1; t += 32) atomicAdd(&s_cnt[wid][s_kc[t]], 1);
    __syncthreads();
    // ---- per-chain exclusive prefix over segments; chain totals ----
    if (tid < NC) {
        int run = 0;
#pragma unroll
        for (int w = 0; w < NW; ++w) {
            int v = s_cnt[w][tid];
            s_cnt[w][tid] = run;
            run += v;
        }
        s_start[tid] = run;  // total per chain (temp)
    }
    __syncthreads();
    // ---- exclusive scan over 100 chain totals (warp 0) ----
    if (wid == 0) {
        int base4 = lane * 4;
        int v0 = 0, v1 = 0, v2 = 0, v3 = 0;
        if (lane < 25) {
            v0 = s_start[base4]; v1 = s_start[base4 + 1];
            v2 = s_start[base4 + 2]; v3 = s_start[base4 + 3];
        }
        int sum = v0 + v1 + v2 + v3;
        int inc = sum;
#pragma unroll
        for (int off = 1; off < 32; off <<= 1) {
            int n = __shfl_up_sync(0xffffffffu, inc, off);
            if (lane >= off) inc += n;
        }
        int ex = inc - sum;
        if (lane < 25) {
            s_start[base4]     = ex;
            s_start[base4 + 1] = ex + v0;
            s_start[base4 + 2] = ex + v0 + v1;
            s_start[base4 + 3] = ex + v0 + v1 + v2;
        }
        if (lane == 24) s_start[NC] = ex + sum;  // == TT
    }
    __syncthreads();
    // ---- add chain bases; assign chain -> half-warp group ----
    if (tid < NC) {
        int st = s_start[tid];
#pragma unroll
        for (int w = 0; w < NW; ++w) s_cnt[w][tid] += st;
        if (s_start[tid + 1] > st) {
            int g = st >> 4;
            if (g > NH - 1) g = NH - 1;
            atomicMin(&s_hwlo[g], st);
        }
    }
    __syncthreads();
    // ---- sort pass 2: fill packed schedule (one 32-batch per warp) ----
    {
        int t = t0 + lane;
        bool valid = t < t1;
        unsigned am = __ballot_sync(0xffffffffu, valid);
        if (valid) {
            int c = s_kc[t];
            unsigned m = __match_any_sync(am, c);
            int rank = __popc(m & ((1u << lane) - 1u));
            int pos = s_cnt[wid][c] + rank;
            int w = t | (c << 9);
            if (pos == s_start[c]) w |= 0x80000000;
            s_ordc[pos] = w;
        }
    }
    // fix up empty groups (suffix fill)
    if (tid == 0) {
        for (int h = NH - 1; h >= 0; --h)
            if (s_hwlo[h] == 0x7fffffff) s_hwlo[h] = s_hwlo[h + 1];
    }
    __syncthreads();

    // ---- sweep: each half-warp walks its schedule range ----
    {
        int h = (wid << 1) | (lane >> 4);
        int lo = s_hwlo[h], hi = s_hwlo[h + 1];
        float A0 = 0.f, A1 = 0.f;
        float4 T = make_float4(0.f, 0.f, 0.f, 0.f);
        int i = lo;
        while (true) {
            unsigned act = __ballot_sync(0xffffffffu, i < hi);
            if (!act) break;
            if (i < hi) {
                int w = s_ordc[i];
                int t = w & 511;
                if (w < 0) {  // first occurrence of a chain: reset alpha
                    int c = (w >> 9) & 127;
                    float2 I = s_init[c];
                    A0 = I.x; A1 = I.y;
                    T = s_T[c];
                }
                float4 zz = s_z[t];
                float z0 = fmaf(zz.z, ab2, zz.x);
                float z1 = fmaf(zz.z, ab2, zz.y);
                float f0 = 1.f + __expf(-z0);    // 1/p0
                float f1 = 1.f + __expf(-z1);    // 1/p1
                float v0 = A0 * f1, v1 = A1 * f0;
                float sS = v0 + v1;
                float Gy = __fdividef(sS, f0 * f1);
                if (la < NA) s_G[t * NA + la] = Gy;
                float r = __fdividef(1.f, sS);
                A0 = fmaf(v0, T.x, v1 * T.y) * r;
                A1 = fmaf(v0, T.z, v1 * T.w) * r;
            }
            ++i;
        }
    }
    __syncthreads();

    // ---- post 1a: half-warp chunk (16 steps) log-prefix, materialized ----
    {
        int h = (wid << 1) | (lane >> 4);
        int c0 = h * CH2;
        int c1 = min(c0 + CH2, TT);
        if (la < NA) {
            float acc = 0.f;
            for (int t = c0; t < c1; ++t) {
                float lgy = __logf(s_G[t * NA + la]);
                s_abil[t * NA + la] = acc;  // prefix BEFORE step t
                acc += lgy;
            }
            s_csum[h][la] = acc;
        }
    }
    __syncthreads();
    if (wid == 0 && lane < NA) {
        float run = -2.5649493574615367f;  // -log(13)
#pragma unroll
        for (int w = 0; w < NH; ++w) {
            s_carry[w][lane] = run;
            run += s_csum[w][lane];
        }
    }
    __syncthreads();

    // ---- post 2: thread-per-row, linear space ----
    {
        int t = tid;
        if (t < TT) {
            int ch = t >> 4;
            float ab[NA], G[NA];
            float M = -1e30f;
#pragma unroll
            for (int a = 0; a < NA; ++a) {
                G[a]  = s_G[t * NA + a];
                ab[a] = s_abil[t * NA + a] + s_carry[ch][a];
                M = fmaxf(M, ab[a]);
            }
            float Sy = 0.f, So = 0.f;
#pragma unroll
            for (int a = 0; a < NA; ++a) {
                float E = __expf(ab[a] - M);
                Sy = fmaf(E, G[a], Sy);
                So = fmaf(E, 1.f - G[a], So);
            }
            bool y = s_z[t].z > 0.f;
            float ly = __logf(Sy), lo = __logf(So), ls = __logf(Sy + So);
            float o0 = (y ? lo : ly) - ls;
            float o1 = (y ? ly : lo) - ls;
            ((float2*)out)[b * TT + t] = make_float2(o0, o1);
        }
    }
}

// ---------------------------------------------------------------------------
// inputs: 0 corr[i32 B,T] 1 kc 2 problem 3 FM[f32 B,T,200]
//         4 trans_logits[f32 100,2,2] 5 obs_logits_problem[f32 10000,2,2]
//         6 obs_logits_kc[f32 100,2,2] 7 init_logits[f32 100,2]
//         8 lr_w[f32 2,200] 9 lr_b[f32 2]     output: f32 [B,T,2]
// ---------------------------------------------------------------------------
extern "C" void kernel_launch(void* const* d_in, const int* in_sizes, int n_in,
                              void* d_out, int out_size) {
    const int*   corr = (const int*)d_in[0];
    const int*   kcp  = (const int*)d_in[1];
    const int*   prob = (const int*)d_in[2];
    const float* FM   = (const float*)d_in[3];
    const float* tl   = (const float*)d_in[4];
    const float* olp  = (const float*)d_in[5];
    const float* olk  = (const float*)d_in[6];
    const float* il   = (const float*)d_in[7];
    const float* lrw  = (const float*)d_in[8];
    const float* lrb  = (const float*)d_in[9];
    float* out = (float*)d_out;

    const int DSMEM = TT * NA * 2 * (int)sizeof(float);  // 52000 B
    cudaFuncSetAttribute(bkt_kernel, cudaFuncAttributeMaxDynamicSharedMemorySize, DSMEM);

    x_kernel<<<(BB * TT / 4 + 7) / 8, 256>>>(FM, lrw, lrb);
    bkt_kernel<<<BB, 512, DSMEM>>>(corr, kcp, prob, tl, olp, olk, il, out);
}

// round 16
// speedup vs baseline: 1.4893x; 1.0370x over previous
#include <cuda_runtime.h>

#define BB 256
#define TT 500
#define NC 100
#define NA 13
#define NW 16          // warps per bkt block
#define CH 32          // timesteps per warp segment for sort (16*32 >= 500)
#define NH 32          // half-warps per block
#define CH2 16         // timesteps per half-warp chunk (32*16 >= 500)

// scratch: x = FM @ lr_w^T + lr_b  [B,T,2]
__device__ float g_x[BB * TT * 2];

// ---------------------------------------------------------------------------
// Kernel 1: x[b,t,o] = sum_f FM[b,t,f] * lr_w[o,f] + lr_b[o]
// Quarter-warp per row: 8 lanes own one row; 7 lane-strided LDG.128,
// 3-stage 8-lane reduction (6 SHFL total/warp), one 4-lane STG.64.
// ---------------------------------------------------------------------------
__global__ void __launch_bounds__(256) x_kernel(const float* __restrict__ FM,
                                                const float* __restrict__ lr_w,
                                                const float* __restrict__ lr_b) {
    __shared__ float4 w0[50], w1[50];
    int tid = threadIdx.x;
    if (tid < 50) {
        w0[tid] = ((const float4*)lr_w)[tid];
        w1[tid] = ((const float4*)lr_w)[50 + tid];
    }
    __syncthreads();
    const int lane = tid & 31;
    const int la = lane & 7;                    // lane within quarter
    const int r = (blockIdx.x * 8 + (tid >> 5)) * 4 + (lane >> 3);
    const float4* fp = (const float4*)FM + (size_t)r * 50;

    // 7 lane-strided loads (k=6 covers f4 indices 48,49 on la<2)
    float4 A0 = __ldg(fp + la);
    float4 A1 = __ldg(fp + la + 8);
    float4 A2 = __ldg(fp + la + 16);
    float4 A3 = __ldg(fp + la + 24);
    float4 A4 = __ldg(fp + la + 32);
    float4 A5 = __ldg(fp + la + 40);
    float4 A6;
    const bool t2 = la < 2;
    if (t2) A6 = __ldg(fp + la + 48);

    float4 u, s;
    float d0a = 0.f, d1a = 0.f, d0b = 0.f, d1b = 0.f;
    u = w0[la];      s = w1[la];
    d0a += A0.x*u.x + A0.y*u.y + A0.z*u.z + A0.w*u.w;
    d1a += A0.x*s.x + A0.y*s.y + A0.z*s.z + A0.w*s.w;
    u = w0[la + 8];  s = w1[la + 8];
    d0b += A1.x*u.x + A1.y*u.y + A1.z*u.z + A1.w*u.w;
    d1b += A1.x*s.x + A1.y*s.y + A1.z*s.z + A1.w*s.w;
    u = w0[la + 16]; s = w1[la + 16];
    d0a += A2.x*u.x + A2.y*u.y + A2.z*u.z + A2.w*u.w;
    d1a += A2.x*s.x + A2.y*s.y + A2.z*s.z + A2.w*s.w;
    u = w0[la + 24]; s = w1[la + 24];
    d0b += A3.x*u.x + A3.y*u.y + A3.z*u.z + A3.w*u.w;
    d1b += A3.x*s.x + A3.y*s.y + A3.z*s.z + A3.w*s.w;
    u = w0[la + 32]; s = w1[la + 32];
    d0a += A4.x*u.x + A4.y*u.y + A4.z*u.z + A4.w*u.w;
    d1a += A4.x*s.x + A4.y*s.y + A4.z*s.z + A4.w*s.w;
    u = w0[la + 40]; s = w1[la + 40];
    d0b += A5.x*u.x + A5.y*u.y + A5.z*u.z + A5.w*u.w;
    d1b += A5.x*s.x + A5.y*s.y + A5.z*s.z + A5.w*s.w;
    if (t2) {
        u = w0[la + 48]; s = w1[la + 48];
        d0a += A6.x*u.x + A6.y*u.y + A6.z*u.z + A6.w*u.w;
        d1a += A6.x*s.x + A6.y*s.y + A6.z*s.z + A6.w*s.w;
    }
    float d0 = d0a + d0b, d1 = d1a + d1b;
#pragma unroll
    for (int off = 1; off < 8; off <<= 1) {   // reduce within 8-lane group
        d0 += __shfl_xor_sync(0xffffffffu, d0, off);
        d1 += __shfl_xor_sync(0xffffffffu, d1, off);
    }
    if (la == 0) {
        ((float2*)g_x)[r] = make_float2(d0 + __ldg(lr_b), d1 + __ldg(lr_b + 1));
    }
}

// ---------------------------------------------------------------------------
// Kernel 2 (fused): per-batch block, 16 warps / 512 threads. (unchanged R13)
//   1) stage z-table + per-chain tables
//   2) parallel stable counting sort -> packed flat schedule
//   3) sweep: 32 half-warps walk contiguous schedule ranges, alpha in regs
//   4) post 1a: 32 half-warp chunks (16 steps) log-prefix -> s_abil
//   5) post 2: thread-per-row linear-space lse
// dynamic smem: s_G[TT*NA] + s_abil[TT*NA] = 52000 B
// ---------------------------------------------------------------------------
__global__ void __launch_bounds__(512) bkt_kernel(
    const int* __restrict__ corr, const int* __restrict__ kc,
    const int* __restrict__ prob, const float* __restrict__ trans_logits,
    const float* __restrict__ olp, const float* __restrict__ olk,
    const float* __restrict__ init_logits, float* __restrict__ out) {
    extern __shared__ float dsm[];
    float* s_G    = dsm;            // Gy per (t, a)            26000 B
    float* s_abil = dsm + TT * NA;  // chunk-local prefix       26000 B

    __shared__ float4 s_z[TT];           // (sy*D0, sy*D1, sy, 0)   8000 B
    __shared__ float4 s_T[NC];           // trans probs             1600 B
    __shared__ float2 s_init[NC];        //                          800 B
    __shared__ float2 s_okd[NC];         // olk deltas               800 B
    __shared__ int    s_kc[TT];          //                         2000 B
    __shared__ int    s_ordc[TT];        // packed schedule         2000 B
    __shared__ int    s_start[NC + 4];   //                          416 B
    __shared__ int    s_cnt[NW][NC];     //                         6400 B
    __shared__ int    s_hwlo[NH + 1];    // half-warp ranges         132 B
    __shared__ float  s_csum[NH][NA];
    __shared__ float  s_carry[NH][NA];

    const int b = blockIdx.x;
    const int tid = threadIdx.x;
    const int wid = tid >> 5;
    const int lane = tid & 31;
    const int la = lane & 15;                 // lane within half-warp
    const int laneA = (la < NA) ? la : 0;
    const float ab2 = 2.f * (-3.0f + 0.5f * (float)laneA);
    const int t0 = wid * CH;
    const int t1 = min(t0 + CH, TT);

    const float4* olp4 = (const float4*)olp;
    const float4* olk4 = (const float4*)olk;
    const float4* tl4  = (const float4*)trans_logits;
    const float2* gx2  = (const float2*)g_x;

    // ---- stage chain tables; zero histograms; init group bounds ----
    for (int i = tid; i < NW * NC; i += 512) (&s_cnt[0][0])[i] = 0;
    if (tid < NH) s_hwlo[tid] = 0x7fffffff;
    if (tid == NH) s_hwlo[NH] = TT;
    if (tid < NC) {
        float4 t = __ldg(tl4 + tid);
        float m0 = fmaxf(t.x, t.z), m1 = fmaxf(t.y, t.w);
        float e00 = __expf(t.x - m0), e10 = __expf(t.z - m0);
        float e01 = __expf(t.y - m1), e11 = __expf(t.w - m1);
        float r0 = __fdividef(1.f, e00 + e10);
        float r1 = __fdividef(1.f, e01 + e11);
        s_T[tid] = make_float4(e00 * r0, e01 * r1, e10 * r0, e11 * r1);
        float2 il = ((const float2*)init_logits)[tid];
        float m = fmaxf(il.x, il.y);
        float ex = __expf(il.x - m), ey = __expf(il.y - m);
        float ri = __fdividef(1.f, ex + ey);
        s_init[tid] = make_float2(ex * ri, ey * ri);
        float4 ok = __ldg(olk4 + tid);
        s_okd[tid] = make_float2(ok.y - ok.x, ok.w - ok.z);
    }
    __syncthreads();

    // ---- stage z table + kc ----
    for (int i = tid; i < TT; i += 512) {
        int c = kc[b * TT + i];
        int p = prob[b * TT + i];
        int y = corr[b * TT + i];
        s_kc[i] = c;
        float4 op = __ldg(olp4 + p);
        float2 okd = s_okd[c];
        float2 xv = gx2[b * TT + i];
        float sy = y ? 1.f : -1.f;
        float D0 = (op.y - op.x) + okd.x - 2.f * xv.x;
        float D1 = (op.w - op.z) + okd.y - 2.f * xv.y;
        s_z[i] = make_float4(sy * D0, sy * D1, sy, 0.f);
    }
    __syncthreads();

    // ---- sort pass 1: per-segment histogram ----
    for (int t = t0 + lane; t < t1; t += 32) atomicAdd(&s_cnt[wid][s_kc[t]], 1);
    __syncthreads();
    // ---- per-chain exclusive prefix over segments; chain totals ----
    if (tid < NC) {
        int run = 0;
#pragma unroll
        for (int w = 0; w < NW; ++w) {
            int v = s_cnt[w][tid];
            s_cnt[w][tid] = run;
            run += v;
        }
        s_start[tid] = run;  // total per chain (temp)
    }
    __syncthreads();
    // ---- exclusive scan over 100 chain totals (warp 0) ----
    if (wid == 0) {
        int base4 = lane * 4;
        int v0 = 0, v1 = 0, v2 = 0, v3 = 0;
        if (lane < 25) {
            v0 = s_start[base4]; v1 = s_start[base4 + 1];
            v2 = s_start[base4 + 2]; v3 = s_start[base4 + 3];
        }
        int sum = v0 + v1 + v2 + v3;
        int inc = sum;
#pragma unroll
        for (int off = 1; off < 32; off <<= 1) {
            int n = __shfl_up_sync(0xffffffffu, inc, off);
            if (lane >= off) inc += n;
        }
        int ex = inc - sum;
        if (lane < 25) {
            s_start[base4]     = ex;
            s_start[base4 + 1] = ex + v0;
            s_start[base4 + 2] = ex + v0 + v1;
            s_start[base4 + 3] = ex + v0 + v1 + v2;
        }
        if (lane == 24) s_start[NC] = ex + sum;  // == TT
    }
    __syncthreads();
    // ---- add chain bases; assign chain -> half-warp group ----
    if (tid < NC) {
        int st = s_start[tid];
#pragma unroll
        for (int w = 0; w < NW; ++w) s_cnt[w][tid] += st;
        if (s_start[tid + 1] > st) {
            int g = st >> 4;
            if (g > NH - 1) g = NH - 1;
            atomicMin(&s_hwlo[g], st);
        }
    }
    __syncthreads();
    // ---- sort pass 2: fill packed schedule (one 32-batch per warp) ----
    {
        int t = t0 + lane;
        bool valid = t < t1;
        unsigned am = __ballot_sync(0xffffffffu, valid);
        if (valid) {
            int c = s_kc[t];
            unsigned m = __match_any_sync(am, c);
            int rank = __popc(m & ((1u << lane) - 1u));
            int pos = s_cnt[wid][c] + rank;
            int w = t | (c << 9);
            if (pos == s_start[c]) w |= 0x80000000;
            s_ordc[pos] = w;
        }
    }
    // fix up empty groups (suffix fill)
    if (tid == 0) {
        for (int h = NH - 1; h >= 0; --h)
            if (s_hwlo[h] == 0x7fffffff) s_hwlo[h] = s_hwlo[h + 1];
    }
    __syncthreads();

    // ---- sweep: each half-warp walks its schedule range ----
    {
        int h = (wid << 1) | (lane >> 4);
        int lo = s_hwlo[h], hi = s_hwlo[h + 1];
        float A0 = 0.f, A1 = 0.f;
        float4 T = make_float4(0.f, 0.f, 0.f, 0.f);
        int i = lo;
        while (true) {
            unsigned act = __ballot_sync(0xffffffffu, i < hi);
            if (!act) break;
            if (i < hi) {
                int w = s_ordc[i];
                int t = w & 511;
                if (w < 0) {  // first occurrence of a chain: reset alpha
                    int c = (w >> 9) & 127;
                    float2 I = s_init[c];
                    A0 = I.x; A1 = I.y;
                    T = s_T[c];
                }
                float4 zz = s_z[t];
                float z0 = fmaf(zz.z, ab2, zz.x);
                float z1 = fmaf(zz.z, ab2, zz.y);
                float f0 = 1.f + __expf(-z0);    // 1/p0
                float f1 = 1.f + __expf(-z1);    // 1/p1
                float v0 = A0 * f1, v1 = A1 * f0;
                float sS = v0 + v1;
                float Gy = __fdividef(sS, f0 * f1);
                if (la < NA) s_G[t * NA + la] = Gy;
                float r = __fdividef(1.f, sS);
                A0 = fmaf(v0, T.x, v1 * T.y) * r;
                A1 = fmaf(v0, T.z, v1 * T.w) * r;
            }
            ++i;
        }
    }
    __syncthreads();

    // ---- post 1a: half-warp chunk (16 steps) log-prefix, materialized ----
    {
        int h = (wid << 1) | (lane >> 4);
        int c0 = h * CH2;
        int c1 = min(c0 + CH2, TT);
        if (la < NA) {
            float acc = 0.f;
            for (int t = c0; t < c1; ++t) {
                float lgy = __logf(s_G[t * NA + la]);
                s_abil[t * NA + la] = acc;  // prefix BEFORE step t
                acc += lgy;
            }
            s_csum[h][la] = acc;
        }
    }
    __syncthreads();
    if (wid == 0 && lane < NA) {
        float run = -2.5649493574615367f;  // -log(13)
#pragma unroll
        for (int w = 0; w < NH; ++w) {
            s_carry[w][lane] = run;
            run += s_csum[w][lane];
        }
    }
    __syncthreads();

    // ---- post 2: thread-per-row, linear space ----
    {
        int t = tid;
        if (t < TT) {
            int ch = t >> 4;
            float ab[NA], G[NA];
            float M = -1e30f;
#pragma unroll
            for (int a = 0; a < NA; ++a) {
                G[a]  = s_G[t * NA + a];
                ab[a] = s_abil[t * NA + a] + s_carry[ch][a];
                M = fmaxf(M, ab[a]);
            }
            float Sy = 0.f, So = 0.f;
#pragma unroll
            for (int a = 0; a < NA; ++a) {
                float E = __expf(ab[a] - M);
                Sy = fmaf(E, G[a], Sy);
                So = fmaf(E, 1.f - G[a], So);
            }
            bool y = s_z[t].z > 0.f;
            float ly = __logf(Sy), lo = __logf(So), ls = __logf(Sy + So);
            float o0 = (y ? lo : ly) - ls;
            float o1 = (y ? ly : lo) - ls;
            ((float2*)out)[b * TT + t] = make_float2(o0, o1);
        }
    }
}

// ---------------------------------------------------------------------------
// inputs: 0 corr[i32 B,T] 1 kc 2 problem 3 FM[f32 B,T,200]
//         4 trans_logits[f32 100,2,2] 5 obs_logits_problem[f32 10000,2,2]
//         6 obs_logits_kc[f32 100,2,2] 7 init_logits[f32 100,2]
//         8 lr_w[f32 2,200] 9 lr_b[f32 2]     output: f32 [B,T,2]
// ---------------------------------------------------------------------------
extern "C" void kernel_launch(void* const* d_in, const int* in_sizes, int n_in,
                              void* d_out, int out_size) {
    const int*   corr = (const int*)d_in[0];
    const int*   kcp  = (const int*)d_in[1];
    const int*   prob = (const int*)d_in[2];
    const float* FM   = (const float*)d_in[3];
    const float* tl   = (const float*)d_in[4];
    const float* olp  = (const float*)d_in[5];
    const float* olk  = (const float*)d_in[6];
    const float* il   = (const float*)d_in[7];
    const float* lrw  = (const float*)d_in[8];
    const float* lrb  = (const float*)d_in[9];
    float* out = (float*)d_out;

    const int DSMEM = TT * NA * 2 * (int)sizeof(float);  // 52000 B
    cudaFuncSetAttribute(bkt_kernel, cudaFuncAttributeMaxDynamicSharedMemorySize, DSMEM);

    x_kernel<<<BB * TT / 32, 256>>>(FM, lrw, lrb);   // 4 rows/warp, 8 warps/block
    bkt_kernel<<<BB, 512, DSMEM>>>(corr, kcp, prob, tl, olp, olk, il, out);
}

// round 17
// speedup vs baseline: 1.4944x; 1.0035x over previous
#include <cuda_runtime.h>

#define BB 256
#define TT 500
#define NC 100
#define NA 13
#define NWP 8          // prep-role warps (256 threads)
#define CHP 63         // sort segment per prep warp
#define NH 32          // half-warps in k2
#define CH2 16         // steps per half-warp chunk in k2

// scratch
__device__ float  g_x[BB * TT * 2];     // x = FM @ lr_w^T + lr_b
__device__ float4 g_zp[BB * TT];        // partial z: (Dp0, Dp1, sy, 0)
__device__ int    g_ordc[BB * TT];      // packed schedule
__device__ int    g_hwlo[BB][NH + 1];   // half-warp group bounds

// ---------------------------------------------------------------------------
// k1: heterogeneous grid. blockIdx < BB  -> prep role (x-independent work)
//                         blockIdx >= BB -> x role (FM GEMV, quarter-warp rows)
// ---------------------------------------------------------------------------
__global__ void __launch_bounds__(256) k1(
    const float* __restrict__ FM, const float* __restrict__ lr_w,
    const float* __restrict__ lr_b, const int* __restrict__ corr,
    const int* __restrict__ kc, const int* __restrict__ prob,
    const float* __restrict__ olp, const float* __restrict__ olk) {
    __shared__ float4 w0[50], w1[50];
    __shared__ float2 s_okd[NC];
    __shared__ int    s_kc[TT];
    __shared__ int    s_start[NC + 4];
    __shared__ int    s_cnt[NWP][NC];
    __shared__ int    s_hwlo[NH + 1];

    const int tid = threadIdx.x;
    const int wid = tid >> 5;
    const int lane = tid & 31;

    if (blockIdx.x >= BB) {
        // ================= x role =================
        if (tid < 50) {
            w0[tid] = ((const float4*)lr_w)[tid];
            w1[tid] = ((const float4*)lr_w)[50 + tid];
        }
        __syncthreads();
        const int la = lane & 7;
        const int r = (((int)blockIdx.x - BB) * 8 + wid) * 4 + (lane >> 3);
        const float4* fp = (const float4*)FM + (size_t)r * 50;

        float4 A0 = __ldg(fp + la);
        float4 A1 = __ldg(fp + la + 8);
        float4 A2 = __ldg(fp + la + 16);
        float4 A3 = __ldg(fp + la + 24);
        float4 A4 = __ldg(fp + la + 32);
        float4 A5 = __ldg(fp + la + 40);
        float4 A6;
        const bool t2 = la < 2;
        if (t2) A6 = __ldg(fp + la + 48);

        float4 u, s;
        float d0a = 0.f, d1a = 0.f, d0b = 0.f, d1b = 0.f;
        u = w0[la];      s = w1[la];
        d0a += A0.x*u.x + A0.y*u.y + A0.z*u.z + A0.w*u.w;
        d1a += A0.x*s.x + A0.y*s.y + A0.z*s.z + A0.w*s.w;
        u = w0[la + 8];  s = w1[la + 8];
        d0b += A1.x*u.x + A1.y*u.y + A1.z*u.z + A1.w*u.w;
        d1b += A1.x*s.x + A1.y*s.y + A1.z*s.z + A1.w*s.w;
        u = w0[la + 16]; s = w1[la + 16];
        d0a += A2.x*u.x + A2.y*u.y + A2.z*u.z + A2.w*u.w;
        d1a += A2.x*s.x + A2.y*s.y + A2.z*s.z + A2.w*s.w;
        u = w0[la + 24]; s = w1[la + 24];
        d0b += A3.x*u.x + A3.y*u.y + A3.z*u.z + A3.w*u.w;
        d1b += A3.x*s.x + A3.y*s.y + A3.z*s.z + A3.w*s.w;
        u = w0[la + 32]; s = w1[la + 32];
        d0a += A4.x*u.x + A4.y*u.y + A4.z*u.z + A4.w*u.w;
        d1a += A4.x*s.x + A4.y*s.y + A4.z*s.z + A4.w*s.w;
        u = w0[la + 40]; s = w1[la + 40];
        d0b += A5.x*u.x + A5.y*u.y + A5.z*u.z + A5.w*u.w;
        d1b += A5.x*s.x + A5.y*s.y + A5.z*s.z + A5.w*s.w;
        if (t2) {
            u = w0[la + 48]; s = w1[la + 48];
            d0a += A6.x*u.x + A6.y*u.y + A6.z*u.z + A6.w*u.w;
            d1a += A6.x*s.x + A6.y*s.y + A6.z*s.z + A6.w*s.w;
        }
        float d0 = d0a + d0b, d1 = d1a + d1b;
#pragma unroll
        for (int off = 1; off < 8; off <<= 1) {
            d0 += __shfl_xor_sync(0xffffffffu, d0, off);
            d1 += __shfl_xor_sync(0xffffffffu, d1, off);
        }
        if (la == 0) {
            ((float2*)g_x)[r] = make_float2(d0 + __ldg(lr_b), d1 + __ldg(lr_b + 1));
        }
        return;
    }

    // ================= prep role =================
    const int b = blockIdx.x;
    const int t0 = wid * CHP;
    const int t1 = min(t0 + CHP, TT);

    for (int i = tid; i < NWP * NC; i += 256) (&s_cnt[0][0])[i] = 0;
    if (tid < NH) s_hwlo[tid] = 0x7fffffff;
    if (tid == NH) s_hwlo[NH] = TT;
    if (tid < NC) {
        float4 ok = __ldg((const float4*)olk + tid);
        s_okd[tid] = make_float2(ok.y - ok.x, ok.w - ok.z);
    }
    __syncthreads();

    // partial z table (no x): (Dp0, Dp1, sy); also stage kc
    for (int i = tid; i < TT; i += 256) {
        int c = kc[b * TT + i];
        int p = prob[b * TT + i];
        int y = corr[b * TT + i];
        s_kc[i] = c;
        float4 op = __ldg((const float4*)olp + p);
        float2 okd = s_okd[c];
        float sy = y ? 1.f : -1.f;
        g_zp[b * TT + i] = make_float4((op.y - op.x) + okd.x,
                                       (op.w - op.z) + okd.y, sy, 0.f);
    }
    __syncthreads();

    // counting sort pass 1
    for (int t = t0 + lane; t < t1; t += 32) atomicAdd(&s_cnt[wid][s_kc[t]], 1);
    __syncthreads();
    if (tid < NC) {
        int run = 0;
#pragma unroll
        for (int w = 0; w < NWP; ++w) {
            int v = s_cnt[w][tid];
            s_cnt[w][tid] = run;
            run += v;
        }
        s_start[tid] = run;  // chain totals (temp)
    }
    __syncthreads();
    if (wid == 0) {
        int base4 = lane * 4;
        int v0 = 0, v1 = 0, v2 = 0, v3 = 0;
        if (lane < 25) {
            v0 = s_start[base4]; v1 = s_start[base4 + 1];
            v2 = s_start[base4 + 2]; v3 = s_start[base4 + 3];
        }
        int sum = v0 + v1 + v2 + v3;
        int inc = sum;
#pragma unroll
        for (int off = 1; off < 32; off <<= 1) {
            int n = __shfl_up_sync(0xffffffffu, inc, off);
            if (lane >= off) inc += n;
        }
        int ex = inc - sum;
        if (lane < 25) {
            s_start[base4]     = ex;
            s_start[base4 + 1] = ex + v0;
            s_start[base4 + 2] = ex + v0 + v1;
            s_start[base4 + 3] = ex + v0 + v1 + v2;
        }
        if (lane == 24) s_start[NC] = ex + sum;  // == TT
    }
    __syncthreads();
    if (tid < NC) {
        int st = s_start[tid];
#pragma unroll
        for (int w = 0; w < NWP; ++w) s_cnt[w][tid] += st;
        if (s_start[tid + 1] > st) {
            int g = st >> 4;
            if (g > NH - 1) g = NH - 1;
            atomicMin(&s_hwlo[g], st);
        }
    }
    __syncthreads();
    // pass 2: fill packed schedule straight to global
    for (int base = t0; base < t1; base += 32) {
        int t = base + lane;
        bool valid = t < t1;
        unsigned am = __ballot_sync(0xffffffffu, valid);
        if (valid) {
            int c = s_kc[t];
            unsigned m = __match_any_sync(am, c);
            int rank = __popc(m & ((1u << lane) - 1u));
            int b0 = s_cnt[wid][c];
            int w = t | (c << 9);
            if (b0 + rank == s_start[c]) w |= 0x80000000;
            g_ordc[b * TT + b0 + rank] = w;
            int leader = 31 - __clz(m);
            if (lane == leader) s_cnt[wid][c] = b0 + __popc(m);
        }
        __syncwarp();
    }
    if (tid == 0) {
        for (int h = NH - 1; h >= 0; --h)
            if (s_hwlo[h] == 0x7fffffff) s_hwlo[h] = s_hwlo[h + 1];
    }
    __syncthreads();
    if (tid <= NH) g_hwlo[b][tid] = s_hwlo[tid];
}

// ---------------------------------------------------------------------------
// k2: per-batch block (512 thr). Fold x into z; half-warp sweep over the
// prebuilt schedule (prefetched, no per-iter ballot); interleaved (Gy,abil)
// float2 smem; chunked log-prefix; thread-per-row linear-space lse.
// dynamic smem: s_ga[TT*NA] float2 = 52000 B
// ---------------------------------------------------------------------------
__global__ void __launch_bounds__(512) k2(
    const float* __restrict__ trans_logits,
    const float* __restrict__ init_logits, float* __restrict__ out) {
    extern __shared__ float dsm[];
    float2* s_ga = (float2*)dsm;         // (Gy, abil) per (t, a)   52000 B

    __shared__ float4 s_z[512];          // (D0, D1, sy, 0), padded  8192 B
    __shared__ int    s_ordc[TT];
    __shared__ int    s_hwlo[NH + 1];
    __shared__ float4 s_T[NC];
    __shared__ float2 s_init[NC];
    __shared__ float  s_csum[NH][NA];
    __shared__ float  s_carry[NH][NA];

    const int b = blockIdx.x;
    const int tid = threadIdx.x;
    const int wid = tid >> 5;
    const int lane = tid & 31;
    const int la = lane & 15;
    const int laneA = (la < NA) ? la : 0;
    const float ab2 = 2.f * (-3.0f + 0.5f * (float)laneA);

    // ---- stage ----
    for (int i = tid; i < TT; i += 512) {
        float4 zp = g_zp[b * TT + i];
        float2 xv = ((const float2*)g_x)[b * TT + i];
        float D0 = zp.z * (zp.x - 2.f * xv.x);
        float D1 = zp.z * (zp.y - 2.f * xv.y);
        s_z[i] = make_float4(D0, D1, zp.z, 0.f);
        s_ordc[i] = g_ordc[b * TT + i];
    }
    if (tid >= TT && tid < 512) s_z[tid] = make_float4(0.f, 0.f, 1.f, 0.f);
    if (tid <= NH) s_hwlo[tid] = g_hwlo[b][tid];
    if (tid < NC) {
        float4 t = __ldg((const float4*)trans_logits + tid);
        float m0 = fmaxf(t.x, t.z), m1 = fmaxf(t.y, t.w);
        float e00 = __expf(t.x - m0), e10 = __expf(t.z - m0);
        float e01 = __expf(t.y - m1), e11 = __expf(t.w - m1);
        float r0 = __fdividef(1.f, e00 + e10);
        float r1 = __fdividef(1.f, e01 + e11);
        s_T[tid] = make_float4(e00 * r0, e01 * r1, e10 * r0, e11 * r1);
        float2 il = ((const float2*)init_logits)[tid];
        float m = fmaxf(il.x, il.y);
        float ex = __expf(il.x - m), ey = __expf(il.y - m);
        float ri = __fdividef(1.f, ex + ey);
        s_init[tid] = make_float2(ex * ri, ey * ri);
    }
    __syncthreads();

    // ---- sweep: half-warp walks its range; prefetch next entry ----
    {
        int h = (wid << 1) | (lane >> 4);
        int lo = s_hwlo[h], hi = s_hwlo[h + 1];
        int len = hi - lo;
        int lenmax = max(len, __shfl_xor_sync(0xffffffffu, len, 16));
        float A0 = 0.f, A1 = 0.f;
        float4 T = make_float4(0.f, 0.f, 0.f, 0.f);
        int safe_lo = (lo < TT) ? lo : 0;
        int i = lo;
        int w = s_ordc[safe_lo];
        float4 zz = s_z[w & 511];
        for (int k = 0; k < lenmax; ++k) {
            int inx = (i + 1 < hi) ? i + 1 : safe_lo;
            int wn = s_ordc[inx];
            float4 zn = s_z[wn & 511];
            if (k < len) {
                if (w < 0) {  // first occurrence of chain: reset alpha
                    int c = (w >> 9) & 127;
                    float2 I = s_init[c];
                    A0 = I.x; A1 = I.y;
                    T = s_T[c];
                }
                int t = w & 511;
                float z0 = fmaf(zz.z, ab2, zz.x);
                float z1 = fmaf(zz.z, ab2, zz.y);
                float f0 = 1.f + __expf(-z0);    // 1/p0
                float f1 = 1.f + __expf(-z1);    // 1/p1
                float v0 = A0 * f1, v1 = A1 * f0;
                float sS = v0 + v1;
                float Gy = __fdividef(sS, f0 * f1);
                if (la < NA) s_ga[t * NA + la].x = Gy;
                float r = __fdividef(1.f, sS);
                A0 = fmaf(v0, T.x, v1 * T.y) * r;
                A1 = fmaf(v0, T.z, v1 * T.w) * r;
            }
            w = wn; zz = zn; ++i;
        }
    }
    __syncthreads();

    // ---- post 1a: half-warp chunk (16 steps) log-prefix into .y ----
    {
        int h = (wid << 1) | (lane >> 4);
        int c0 = h * CH2;
        int c1 = min(c0 + CH2, TT);
        if (la < NA) {
            float acc = 0.f;
            for (int t = c0; t < c1; ++t) {
                float lgy = __logf(s_ga[t * NA + la].x);
                s_ga[t * NA + la].y = acc;  // prefix BEFORE step t
                acc += lgy;
            }
            s_csum[h][la] = acc;
        }
    }
    __syncthreads();
    if (wid == 0 && lane < NA) {
        float run = -2.5649493574615367f;  // -log(13)
#pragma unroll
        for (int w = 0; w < NH; ++w) {
            s_carry[w][lane] = run;
            run += s_csum[w][lane];
        }
    }
    __syncthreads();

    // ---- post 2: thread-per-row, linear space ----
    {
        int t = tid;
        if (t < TT) {
            int ch = t >> 4;
            float ab[NA], G[NA];
            float M = -1e30f;
#pragma unroll
            for (int a = 0; a < NA; ++a) {
                float2 ga = s_ga[t * NA + a];
                G[a]  = ga.x;
                ab[a] = ga.y + s_carry[ch][a];
                M = fmaxf(M, ab[a]);
            }
            float Sy = 0.f, So = 0.f;
#pragma unroll
            for (int a = 0; a < NA; ++a) {
                float E = __expf(ab[a] - M);
                Sy = fmaf(E, G[a], Sy);
                So = fmaf(E, 1.f - G[a], So);
            }
            bool y = s_z[t].z > 0.f;
            float ly = __logf(Sy), lo = __logf(So), ls = __logf(Sy + So);
            float o0 = (y ? lo : ly) - ls;
            float o1 = (y ? ly : lo) - ls;
            ((float2*)out)[b * TT + t] = make_float2(o0, o1);
        }
    }
}

// ---------------------------------------------------------------------------
// inputs: 0 corr[i32 B,T] 1 kc 2 problem 3 FM[f32 B,T,200]
//         4 trans_logits[f32 100,2,2] 5 obs_logits_problem[f32 10000,2,2]
//         6 obs_logits_kc[f32 100,2,2] 7 init_logits[f32 100,2]
//         8 lr_w[f32 2,200] 9 lr_b[f32 2]     output: f32 [B,T,2]
// ---------------------------------------------------------------------------
extern "C" void kernel_launch(void* const* d_in, const int* in_sizes, int n_in,
                              void* d_out, int out_size) {
    const int*   corr = (const int*)d_in[0];
    const int*   kcp  = (const int*)d_in[1];
    const int*   prob = (const int*)d_in[2];
    const float* FM   = (const float*)d_in[3];
    const float* tl   = (const float*)d_in[4];
    const float* olp  = (const float*)d_in[5];
    const float* olk  = (const float*)d_in[6];
    const float* il   = (const float*)d_in[7];
    const float* lrw  = (const float*)d_in[8];
    const float* lrb  = (const float*)d_in[9];
    float* out = (float*)d_out;

    const int DSMEM = TT * NA * 2 * (int)sizeof(float);  // 52000 B
    cudaFuncSetAttribute(k2, cudaFuncAttributeMaxDynamicSharedMemorySize, DSMEM);

    // k1: 256 prep blocks + 4000 x blocks (prep dispatched first)
    k1<<<BB + BB * TT / 32, 256>>>(FM, lrw, lrb, corr, kcp, prob, olp, olk);
    k2<<<BB, 512, DSMEM>>>(tl, il, out);
}